// round 5
// baseline (speedup 1.0000x reference)
#include <cuda_runtime.h>
#include <math.h>

#define MM 4096
#define DD 2048
#define INV_SQRT_M 0.015625f   // 1/sqrt(4096) exact

// ---------------- device scratch ----------------
__device__ float g_qt[MM];
__device__ float g_k[MM];
__device__ float g_v[MM];
__device__ float g_it, g_ft, g_ot;
__device__ float g_kqt, g_denom;

// ---------------- kernel 1: fused q/k/v matvecs + gates ----------------
// 256-thread blocks. b < 2048: block handles rows 2b and 2b+1 of Wq/Wk/Wv
// (12 front-batched streaming loads per thread, one combined block reduce).
// b == 2048: gates from Wi/Wf/Wo (single triple).
__global__ __launch_bounds__(256) void mv_kernel(
    const float* __restrict__ x,
    const float* __restrict__ Wq, const float* __restrict__ bq,
    const float* __restrict__ Wk, const float* __restrict__ bk,
    const float* __restrict__ Wv, const float* __restrict__ bV,
    const float* __restrict__ Wi, const float* __restrict__ bi,
    const float* __restrict__ Wf, const float* __restrict__ bf,
    const float* __restrict__ Wo, const float* __restrict__ bo)
{
    const int b = blockIdx.x;
    const int t = threadIdx.x;

    const float4* x4 = reinterpret_cast<const float4*>(x);
    const float4 x0 = x4[t];
    const float4 x1 = x4[t + 256];

    __shared__ float ws[6][8];

    if (b < MM / 2) {
        const int r0 = b * 2;
        const int r1 = r0 + 1;
        const float4* A0 = reinterpret_cast<const float4*>(Wq + (size_t)r0 * DD);
        const float4* A1 = reinterpret_cast<const float4*>(Wq + (size_t)r1 * DD);
        const float4* B0 = reinterpret_cast<const float4*>(Wk + (size_t)r0 * DD);
        const float4* B1 = reinterpret_cast<const float4*>(Wk + (size_t)r1 * DD);
        const float4* C0 = reinterpret_cast<const float4*>(Wv + (size_t)r0 * DD);
        const float4* C1 = reinterpret_cast<const float4*>(Wv + (size_t)r1 * DD);

        // 12 independent streaming loads, front-batched
        float4 a00 = __ldcs(&A0[t]);       float4 a01 = __ldcs(&A0[t + 256]);
        float4 k00 = __ldcs(&B0[t]);       float4 k01 = __ldcs(&B0[t + 256]);
        float4 v00 = __ldcs(&C0[t]);       float4 v01 = __ldcs(&C0[t + 256]);
        float4 a10 = __ldcs(&A1[t]);       float4 a11 = __ldcs(&A1[t + 256]);
        float4 k10 = __ldcs(&B1[t]);       float4 k11 = __ldcs(&B1[t + 256]);
        float4 v10 = __ldcs(&C1[t]);       float4 v11 = __ldcs(&C1[t + 256]);

        float s0 = a00.x*x0.x + a00.y*x0.y + a00.z*x0.z + a00.w*x0.w
                 + a01.x*x1.x + a01.y*x1.y + a01.z*x1.z + a01.w*x1.w;
        float s1 = k00.x*x0.x + k00.y*x0.y + k00.z*x0.z + k00.w*x0.w
                 + k01.x*x1.x + k01.y*x1.y + k01.z*x1.z + k01.w*x1.w;
        float s2 = v00.x*x0.x + v00.y*x0.y + v00.z*x0.z + v00.w*x0.w
                 + v01.x*x1.x + v01.y*x1.y + v01.z*x1.z + v01.w*x1.w;
        float s3 = a10.x*x0.x + a10.y*x0.y + a10.z*x0.z + a10.w*x0.w
                 + a11.x*x1.x + a11.y*x1.y + a11.z*x1.z + a11.w*x1.w;
        float s4 = k10.x*x0.x + k10.y*x0.y + k10.z*x0.z + k10.w*x0.w
                 + k11.x*x1.x + k11.y*x1.y + k11.z*x1.z + k11.w*x1.w;
        float s5 = v10.x*x0.x + v10.y*x0.y + v10.z*x0.z + v10.w*x0.w
                 + v11.x*x1.x + v11.y*x1.y + v11.z*x1.z + v11.w*x1.w;

        #pragma unroll
        for (int o = 16; o > 0; o >>= 1) {
            s0 += __shfl_down_sync(0xFFFFFFFFu, s0, o);
            s1 += __shfl_down_sync(0xFFFFFFFFu, s1, o);
            s2 += __shfl_down_sync(0xFFFFFFFFu, s2, o);
            s3 += __shfl_down_sync(0xFFFFFFFFu, s3, o);
            s4 += __shfl_down_sync(0xFFFFFFFFu, s4, o);
            s5 += __shfl_down_sync(0xFFFFFFFFu, s5, o);
        }
        if ((t & 31) == 0) {
            const int w = t >> 5;
            ws[0][w] = s0; ws[1][w] = s1; ws[2][w] = s2;
            ws[3][w] = s3; ws[4][w] = s4; ws[5][w] = s5;
        }
        __syncthreads();
        if (t < 8) {
            float r0v = ws[0][t], r1v = ws[1][t], r2v = ws[2][t];
            float r3v = ws[3][t], r4v = ws[4][t], r5v = ws[5][t];
            #pragma unroll
            for (int o = 4; o > 0; o >>= 1) {
                r0v += __shfl_down_sync(0xFFu, r0v, o, 8);
                r1v += __shfl_down_sync(0xFFu, r1v, o, 8);
                r2v += __shfl_down_sync(0xFFu, r2v, o, 8);
                r3v += __shfl_down_sync(0xFFu, r3v, o, 8);
                r4v += __shfl_down_sync(0xFFu, r4v, o, 8);
                r5v += __shfl_down_sync(0xFFu, r5v, o, 8);
            }
            if (t == 0) {
                g_qt[r0] = r0v + bq[r0];
                g_k[r0]  = INV_SQRT_M * (r1v + bk[r0]);
                g_v[r0]  = r2v + bV[r0];
                g_qt[r1] = r3v + bq[r1];
                g_k[r1]  = INV_SQRT_M * (r4v + bk[r1]);
                g_v[r1]  = r5v + bV[r1];
            }
        }
    } else {
        // gate block
        const float4* A4 = reinterpret_cast<const float4*>(Wi);
        const float4* B4 = reinterpret_cast<const float4*>(Wf);
        const float4* C4 = reinterpret_cast<const float4*>(Wo);
        float4 a0 = __ldcs(&A4[t]); float4 a1 = __ldcs(&A4[t + 256]);
        float4 k0 = __ldcs(&B4[t]); float4 k1 = __ldcs(&B4[t + 256]);
        float4 v0 = __ldcs(&C4[t]); float4 v1 = __ldcs(&C4[t + 256]);

        float sa = a0.x*x0.x + a0.y*x0.y + a0.z*x0.z + a0.w*x0.w
                 + a1.x*x1.x + a1.y*x1.y + a1.z*x1.z + a1.w*x1.w;
        float sk = k0.x*x0.x + k0.y*x0.y + k0.z*x0.z + k0.w*x0.w
                 + k1.x*x1.x + k1.y*x1.y + k1.z*x1.z + k1.w*x1.w;
        float sv = v0.x*x0.x + v0.y*x0.y + v0.z*x0.z + v0.w*x0.w
                 + v1.x*x1.x + v1.y*x1.y + v1.z*x1.z + v1.w*x1.w;

        #pragma unroll
        for (int o = 16; o > 0; o >>= 1) {
            sa += __shfl_down_sync(0xFFFFFFFFu, sa, o);
            sk += __shfl_down_sync(0xFFFFFFFFu, sk, o);
            sv += __shfl_down_sync(0xFFFFFFFFu, sv, o);
        }
        if ((t & 31) == 0) {
            const int w = t >> 5;
            ws[0][w] = sa; ws[1][w] = sk; ws[2][w] = sv;
        }
        __syncthreads();
        if (t < 8) {
            float ra = ws[0][t], rk = ws[1][t], rv = ws[2][t];
            #pragma unroll
            for (int o = 4; o > 0; o >>= 1) {
                ra += __shfl_down_sync(0xFFu, ra, o, 8);
                rk += __shfl_down_sync(0xFFu, rk, o, 8);
                rv += __shfl_down_sync(0xFFu, rv, o, 8);
            }
            if (t == 0) {
                g_it = expf(ra + bi[0]);
                g_ft = expf(rk + bf[0]);
                float z = rv + bo[0];
                g_ot = 1.0f / (1.0f + expf(-z));
            }
        }
    }
}

// ---------------- kernel 2: n-update + tiny reductions ----------------
__global__ __launch_bounds__(1024) void nred_kernel(
    const float* __restrict__ n_prev, float* __restrict__ out_n)
{
    const int t = threadIdx.x;
    const float ft = g_ft, it = g_it;
    float kqt = 0.f, nqt = 0.f;
    #pragma unroll
    for (int u = 0; u < MM / 1024; u++) {
        int i = t + u * 1024;
        float k = g_k[i];
        float q = g_qt[i];
        kqt += k * q;
        float n = ft * n_prev[i] + it * k;
        out_n[i] = n;
        nqt += n * q;
    }
    #pragma unroll
    for (int o = 16; o > 0; o >>= 1) {
        kqt += __shfl_down_sync(0xFFFFFFFFu, kqt, o);
        nqt += __shfl_down_sync(0xFFFFFFFFu, nqt, o);
    }
    __shared__ float sk[32], sn[32];
    if ((t & 31) == 0) { sk[t >> 5] = kqt; sn[t >> 5] = nqt; }
    __syncthreads();
    if (t < 32) {
        float a = sk[t], b = sn[t];
        #pragma unroll
        for (int o = 16; o > 0; o >>= 1) {
            a += __shfl_down_sync(0xFFFFFFFFu, a, o);
            b += __shfl_down_sync(0xFFFFFFFFu, b, o);
        }
        if (t == 0) {
            g_kqt = a;
            g_denom = fmaxf(fabsf(b), 1.0f);
        }
    }
}

// ---------------- kernel 3: cp stream -> C write + cp@qt + ht ----------------
// 256-thread blocks, 2 rows/block (grid 2048). Each thread: 8 front-batched
// streaming loads (4 float4 per row x 2 rows), 8 streaming stores,
// 2 per-row partial dots, one block reduce (8 warps).
__global__ __launch_bounds__(256) void cp_kernel(
    const float* __restrict__ cp, float* __restrict__ outC,
    float* __restrict__ outH)
{
    const int i0 = blockIdx.x * 2;
    const int i1 = i0 + 1;
    const int t  = threadIdx.x;
    const float ft   = g_ft;
    const float it   = g_it;
    const float itv0 = it * g_v[i0];
    const float itv1 = it * g_v[i1];

    const float4* P0 = reinterpret_cast<const float4*>(cp   + (size_t)i0 * MM);
    const float4* P1 = reinterpret_cast<const float4*>(cp   + (size_t)i1 * MM);
    float4*       O0 = reinterpret_cast<float4*>(outC + (size_t)i0 * MM);
    float4*       O1 = reinterpret_cast<float4*>(outC + (size_t)i1 * MM);
    const float4* k4 = reinterpret_cast<const float4*>(g_k);
    const float4* q4 = reinterpret_cast<const float4*>(g_qt);

    const int j0 = t;
    const int j1 = t + 256;
    const int j2 = t + 512;
    const int j3 = t + 768;

    // 8 independent streaming loads front-batched
    float4 c00 = __ldcs(&P0[j0]); float4 c01 = __ldcs(&P0[j1]);
    float4 c02 = __ldcs(&P0[j2]); float4 c03 = __ldcs(&P0[j3]);
    float4 c10 = __ldcs(&P1[j0]); float4 c11 = __ldcs(&P1[j1]);
    float4 c12 = __ldcs(&P1[j2]); float4 c13 = __ldcs(&P1[j3]);

    float4 k0 = k4[j0], k1 = k4[j1], k2 = k4[j2], k3 = k4[j3];
    float4 q0 = q4[j0], q1 = q4[j1], q2 = q4[j2], q3 = q4[j3];

    float4 o;
    o.x = ft*c00.x + itv0*k0.x; o.y = ft*c00.y + itv0*k0.y;
    o.z = ft*c00.z + itv0*k0.z; o.w = ft*c00.w + itv0*k0.w;
    __stcs(&O0[j0], o);
    o.x = ft*c01.x + itv0*k1.x; o.y = ft*c01.y + itv0*k1.y;
    o.z = ft*c01.z + itv0*k1.z; o.w = ft*c01.w + itv0*k1.w;
    __stcs(&O0[j1], o);
    o.x = ft*c02.x + itv0*k2.x; o.y = ft*c02.y + itv0*k2.y;
    o.z = ft*c02.z + itv0*k2.z; o.w = ft*c02.w + itv0*k2.w;
    __stcs(&O0[j2], o);
    o.x = ft*c03.x + itv0*k3.x; o.y = ft*c03.y + itv0*k3.y;
    o.z = ft*c03.z + itv0*k3.z; o.w = ft*c03.w + itv0*k3.w;
    __stcs(&O0[j3], o);
    o.x = ft*c10.x + itv1*k0.x; o.y = ft*c10.y + itv1*k0.y;
    o.z = ft*c10.z + itv1*k0.z; o.w = ft*c10.w + itv1*k0.w;
    __stcs(&O1[j0], o);
    o.x = ft*c11.x + itv1*k1.x; o.y = ft*c11.y + itv1*k1.y;
    o.z = ft*c11.z + itv1*k1.z; o.w = ft*c11.w + itv1*k1.w;
    __stcs(&O1[j1], o);
    o.x = ft*c12.x + itv1*k2.x; o.y = ft*c12.y + itv1*k2.y;
    o.z = ft*c12.z + itv1*k2.z; o.w = ft*c12.w + itv1*k2.w;
    __stcs(&O1[j2], o);
    o.x = ft*c13.x + itv1*k3.x; o.y = ft*c13.y + itv1*k3.y;
    o.z = ft*c13.z + itv1*k3.z; o.w = ft*c13.w + itv1*k3.w;
    __stcs(&O1[j3], o);

    float s0 = c00.x*q0.x + c00.y*q0.y + c00.z*q0.z + c00.w*q0.w
             + c01.x*q1.x + c01.y*q1.y + c01.z*q1.z + c01.w*q1.w
             + c02.x*q2.x + c02.y*q2.y + c02.z*q2.z + c02.w*q2.w
             + c03.x*q3.x + c03.y*q3.y + c03.z*q3.z + c03.w*q3.w;
    float s1 = c10.x*q0.x + c10.y*q0.y + c10.z*q0.z + c10.w*q0.w
             + c11.x*q1.x + c11.y*q1.y + c11.z*q1.z + c11.w*q1.w
             + c12.x*q2.x + c12.y*q2.y + c12.z*q2.z + c12.w*q2.w
             + c13.x*q3.x + c13.y*q3.y + c13.z*q3.z + c13.w*q3.w;

    #pragma unroll
    for (int o2 = 16; o2 > 0; o2 >>= 1) {
        s0 += __shfl_down_sync(0xFFFFFFFFu, s0, o2);
        s1 += __shfl_down_sync(0xFFFFFFFFu, s1, o2);
    }
    __shared__ float ws0[8], ws1[8];
    if ((t & 31) == 0) { ws0[t >> 5] = s0; ws1[t >> 5] = s1; }
    __syncthreads();
    if (t < 8) {
        float a = ws0[t], b = ws1[t];
        #pragma unroll
        for (int o2 = 4; o2 > 0; o2 >>= 1) {
            a += __shfl_down_sync(0xFFu, a, o2, 8);
            b += __shfl_down_sync(0xFFu, b, o2, 8);
        }
        if (t == 0) {
            const float inv = g_ot / g_denom;
            const float kqt = g_kqt;
            outH[i0] = inv * (ft * a + itv0 * kqt);
            outH[i1] = inv * (ft * b + itv1 * kqt);
        }
    }
}

// ---------------- launch ----------------
extern "C" void kernel_launch(void* const* d_in, const int* in_sizes, int n_in,
                              void* d_out, int out_size)
{
    const float* x      = (const float*)d_in[0];
    const float* cp     = (const float*)d_in[1];
    const float* n_prev = (const float*)d_in[2];
    const float* Wq     = (const float*)d_in[3];
    const float* bq     = (const float*)d_in[4];
    const float* Wk     = (const float*)d_in[5];
    const float* bk     = (const float*)d_in[6];
    const float* Wv     = (const float*)d_in[7];
    const float* bV     = (const float*)d_in[8];
    const float* Wi     = (const float*)d_in[9];
    const float* bi     = (const float*)d_in[10];
    const float* Wf     = (const float*)d_in[11];
    const float* bf     = (const float*)d_in[12];
    const float* Wo     = (const float*)d_in[13];
    const float* bo     = (const float*)d_in[14];

    float* out  = (float*)d_out;
    float* outH = out;                        // ht: M
    float* outC = out + MM;                   // C : M*M
    float* outN = out + MM + (size_t)MM * MM; // n : M

    mv_kernel<<<MM / 2 + 1, 256>>>(x, Wq, bq, Wk, bk, Wv, bV,
                                   Wi, bi, Wf, bf, Wo, bo);
    nred_kernel<<<1, 1024>>>(n_prev, outN);
    cp_kernel<<<MM / 2, 256>>>(cp, outC, outH);
}